// round 1
// baseline (speedup 1.0000x reference)
#include <cuda_runtime.h>

// LJ_8718783611256: log_prob = -(LJ pair potential + harmonic confinement)
// x: (4, 2048, 3) float32, out: (4,) float32
//
// No sqrt needed: pair potential = 4*(inv6^2 - inv6), inv6 = (1/sq)^3,
// sq = squared pair distance.

#define NB   4
#define NPTS 2048
#define TPB  256   // threads per block == i-rows per block == j-tile size
#define JT   256

// ---------------------------------------------------------------------------
// Kernel 1: harmonic term per batch; initializes out[b] = -harm.
// harm = 0.5*k * sum((x - com)^2) = 0.25 * (S2 - (Sx^2+Sy^2+Sz^2)/N), k=0.5
// ---------------------------------------------------------------------------
__global__ __launch_bounds__(TPB) void harm_kernel(const float* __restrict__ x,
                                                   float* __restrict__ out) {
    const int b = blockIdx.x;
    const float* xb = x + b * NPTS * 3;

    float sx = 0.f, sy = 0.f, sz = 0.f, s2 = 0.f;
    for (int i = threadIdx.x; i < NPTS; i += TPB) {
        float px = xb[3 * i + 0];
        float py = xb[3 * i + 1];
        float pz = xb[3 * i + 2];
        sx += px; sy += py; sz += pz;
        s2 = fmaf(px, px, s2);
        s2 = fmaf(py, py, s2);
        s2 = fmaf(pz, pz, s2);
    }

    // warp reduce
    #pragma unroll
    for (int o = 16; o; o >>= 1) {
        sx += __shfl_xor_sync(0xffffffffu, sx, o);
        sy += __shfl_xor_sync(0xffffffffu, sy, o);
        sz += __shfl_xor_sync(0xffffffffu, sz, o);
        s2 += __shfl_xor_sync(0xffffffffu, s2, o);
    }

    __shared__ float red[4][TPB / 32];
    const int w = threadIdx.x >> 5, lane = threadIdx.x & 31;
    if (lane == 0) {
        red[0][w] = sx; red[1][w] = sy; red[2][w] = sz; red[3][w] = s2;
    }
    __syncthreads();

    if (threadIdx.x == 0) {
        float tx = 0.f, ty = 0.f, tz = 0.f, t2 = 0.f;
        #pragma unroll
        for (int k = 0; k < TPB / 32; k++) {
            tx += red[0][k]; ty += red[1][k]; tz += red[2][k]; t2 += red[3][k];
        }
        float com2 = (tx * tx + ty * ty + tz * tz) * (1.0f / NPTS);
        float harm = 0.25f * (t2 - com2);   // 0.5 * SPRING_CONSTANT(=0.5) * sum
        out[b] = -harm;
    }
}

// ---------------------------------------------------------------------------
// Kernel 2: LJ pair sum. grid = (j-chunks, i-chunks, batch).
// Each block: stage JT points (float4) in shared; each thread owns one i-row,
// loops the j-tile (broadcast LDS.128), accumulates sum(inv12), sum(inv6).
// ---------------------------------------------------------------------------
__global__ __launch_bounds__(TPB) void lj_kernel(const float* __restrict__ x,
                                                 float* __restrict__ out) {
    const int b  = blockIdx.z;
    const int i  = blockIdx.y * TPB + threadIdx.x;
    const int j0 = blockIdx.x * JT;
    const float* xb = x + b * NPTS * 3;

    __shared__ float4 sj[JT];
    {
        const int t = threadIdx.x;
        const float* p = xb + (j0 + t) * 3;
        sj[t] = make_float4(p[0], p[1], p[2], 0.f);
    }
    __syncthreads();

    const float xi = xb[3 * i + 0];
    const float yi = xb[3 * i + 1];
    const float zi = xb[3 * i + 2];

    float a12 = 0.f, a6 = 0.f;

    #pragma unroll 8
    for (int jj = 0; jj < JT; jj++) {
        float4 p = sj[jj];
        float dx = xi - p.x;
        float dy = yi - p.y;
        float dz = zi - p.z;
        float sq = dx * dx;
        sq = fmaf(dy, dy, sq);
        sq = fmaf(dz, dz, sq);
        // diagonal (i == j): sq == 0 -> force huge sq so contribution -> 0
        sq = (sq == 0.f) ? 3e38f : sq;
        float inv;
        asm("rcp.approx.f32 %0, %1;" : "=f"(inv) : "f"(sq));
        float i3 = inv * inv * inv;          // d^-6
        a12 = fmaf(i3, i3, a12);             // sum d^-12
        a6 += i3;                            // sum d^-6
    }

    float pot = 4.0f * (a12 - a6);

    // warp reduce
    #pragma unroll
    for (int o = 16; o; o >>= 1)
        pot += __shfl_xor_sync(0xffffffffu, pot, o);

    __shared__ float wsum[TPB / 32];
    const int w = threadIdx.x >> 5, lane = threadIdx.x & 31;
    if (lane == 0) wsum[w] = pot;
    __syncthreads();

    if (threadIdx.x < TPB / 32) {
        float v = wsum[threadIdx.x];
        #pragma unroll
        for (int o = (TPB / 64); o; o >>= 1)
            v += __shfl_xor_sync(0xffu, v, o, TPB / 32);
        if (threadIdx.x == 0)
            atomicAdd(out + b, -0.5f * v);   // ordered-pair sum / 2, negated
    }
}

extern "C" void kernel_launch(void* const* d_in, const int* in_sizes, int n_in,
                              void* d_out, int out_size) {
    const float* x = (const float*)d_in[0];
    float* out = (float*)d_out;

    harm_kernel<<<NB, TPB>>>(x, out);

    dim3 grid(NPTS / JT, NPTS / TPB, NB);   // (8, 8, 4)
    lj_kernel<<<grid, TPB>>>(x, out);
}

// round 2
// speedup vs baseline: 1.3207x; 1.3207x over previous
#include <cuda_runtime.h>

// LJ_8718783611256: log_prob = -(LJ pair potential + harmonic confinement)
// x: (4, 2048, 3) float32, out: (4,) float32
//
// Strategy: packed f32x2 math (2 pairs/lane/iter), diagonal guard only in
// bx==by blocks, harmonic term fused into the same launch, out zero-init via
// cudaMemsetAsync + atomicAdd accumulation.

#define NB     4
#define NPTS   2048
#define TPB    128          // threads per block == i-rows per block
#define JT     128          // j-tile size
#define NCHUNK (NPTS / JT)  // 16

typedef unsigned long long ull;

#define FMA2(d, a, b, c) \
    asm("fma.rn.f32x2 %0, %1, %2, %3;" : "=l"(d) : "l"(a), "l"(b), "l"(c))
#define MUL2(d, a, b) \
    asm("mul.rn.f32x2 %0, %1, %2;" : "=l"(d) : "l"(a), "l"(b))
#define ADD2(d, a, b) \
    asm("add.rn.f32x2 %0, %1, %2;" : "=l"(d) : "l"(a), "l"(b))
#define PACK2(d, lo, hi) \
    asm("mov.b64 %0, {%1, %2};" : "=l"(d) : "f"(lo), "f"(hi))
#define UNPACK2(lo, hi, d) \
    asm("mov.b64 {%0, %1}, %2;" : "=f"(lo), "=f"(hi) : "l"(d))
#define RCP(d, s) \
    asm("rcp.approx.f32 %0, %1;" : "=f"(d) : "f"(s))

template <bool DIAG>
__device__ __forceinline__ void lj_loop(const ull* __restrict__ sx2,
                                        const ull* __restrict__ sy2,
                                        const ull* __restrict__ sz2,
                                        ull xi2, ull yi2, ull zi2,
                                        ull& a12, ull& a6) {
    const ull neg1 = 0xBF800000BF800000ULL;  // (-1.0f, -1.0f)
    #pragma unroll 8
    for (int k = 0; k < JT / 2; k++) {
        ull px = sx2[k];
        ull py = sy2[k];
        ull pz = sz2[k];
        ull dx, dy, dz, sq, t2, i3, inv2;
        FMA2(dx, px, neg1, xi2);             // xi - px   (x2)
        FMA2(dy, py, neg1, yi2);
        FMA2(dz, pz, neg1, zi2);
        MUL2(sq, dx, dx);
        FMA2(sq, dy, dy, sq);
        FMA2(sq, dz, dz, sq);                // squared distance (x2)
        float s0, s1;
        UNPACK2(s0, s1, sq);
        if (DIAG) {
            // i == j gives sq == 0 exactly; push it to huge -> rcp underflows -> 0
            s0 = (s0 == 0.f) ? 3e38f : s0;
            s1 = (s1 == 0.f) ? 3e38f : s1;
        }
        float i0, i1;
        RCP(i0, s0);
        RCP(i1, s1);
        PACK2(inv2, i0, i1);
        MUL2(t2, inv2, inv2);
        MUL2(i3, t2, inv2);                  // d^-6 (x2)
        FMA2(a12, i3, i3, a12);              // sum d^-12
        ADD2(a6, i3, a6);                    // sum d^-6
    }
}

__global__ __launch_bounds__(TPB) void lj_fused_kernel(const float* __restrict__ x,
                                                       float* __restrict__ out) {
    const int b = blockIdx.z;
    const float* xb = x + b * NPTS * 3;
    const int t = threadIdx.x;
    const int w = t >> 5, lane = t & 31;

    // ---------------- harmonic blocks (by == NCHUNK) ----------------
    if (blockIdx.y == NCHUNK) {
        if (blockIdx.x != 0) return;
        float sx = 0.f, sy = 0.f, sz = 0.f, s2 = 0.f;
        for (int i = t; i < NPTS; i += TPB) {
            float px = xb[3 * i + 0];
            float py = xb[3 * i + 1];
            float pz = xb[3 * i + 2];
            sx += px; sy += py; sz += pz;
            s2 = fmaf(px, px, s2);
            s2 = fmaf(py, py, s2);
            s2 = fmaf(pz, pz, s2);
        }
        #pragma unroll
        for (int o = 16; o; o >>= 1) {
            sx += __shfl_xor_sync(0xffffffffu, sx, o);
            sy += __shfl_xor_sync(0xffffffffu, sy, o);
            sz += __shfl_xor_sync(0xffffffffu, sz, o);
            s2 += __shfl_xor_sync(0xffffffffu, s2, o);
        }
        __shared__ float red[4][TPB / 32];
        if (lane == 0) { red[0][w] = sx; red[1][w] = sy; red[2][w] = sz; red[3][w] = s2; }
        __syncthreads();
        if (t == 0) {
            float tx = 0.f, ty = 0.f, tz = 0.f, t2 = 0.f;
            #pragma unroll
            for (int k = 0; k < TPB / 32; k++) {
                tx += red[0][k]; ty += red[1][k]; tz += red[2][k]; t2 += red[3][k];
            }
            float com2 = (tx * tx + ty * ty + tz * tz) * (1.0f / NPTS);
            float harm = 0.25f * (t2 - com2);  // 0.5 * k(=0.5) * sum((x-com)^2)
            atomicAdd(out + b, -harm);
        }
        return;
    }

    // ---------------- LJ tile blocks ----------------
    __shared__ float shx[JT], shy[JT], shz[JT];
    const int j0 = blockIdx.x * JT;
    {
        const float* p = xb + (j0 + t) * 3;
        shx[t] = p[0];
        shy[t] = p[1];
        shz[t] = p[2];
    }
    __syncthreads();

    const int i = blockIdx.y * TPB + t;
    const float xi = xb[3 * i + 0];
    const float yi = xb[3 * i + 1];
    const float zi = xb[3 * i + 2];
    ull xi2, yi2, zi2;
    PACK2(xi2, xi, xi);
    PACK2(yi2, yi, yi);
    PACK2(zi2, zi, zi);

    ull a12 = 0ull, a6 = 0ull;
    const ull* sx2 = (const ull*)shx;
    const ull* sy2 = (const ull*)shy;
    const ull* sz2 = (const ull*)shz;

    if (blockIdx.x == blockIdx.y)
        lj_loop<true>(sx2, sy2, sz2, xi2, yi2, zi2, a12, a6);
    else
        lj_loop<false>(sx2, sy2, sz2, xi2, yi2, zi2, a12, a6);

    float a12l, a12h, a6l, a6h;
    UNPACK2(a12l, a12h, a12);
    UNPACK2(a6l, a6h, a6);
    float pot = 4.0f * ((a12l + a12h) - (a6l + a6h));

    #pragma unroll
    for (int o = 16; o; o >>= 1)
        pot += __shfl_xor_sync(0xffffffffu, pot, o);

    __shared__ float wsum[TPB / 32];
    if (lane == 0) wsum[w] = pot;
    __syncthreads();

    if (t == 0) {
        float v = 0.f;
        #pragma unroll
        for (int k = 0; k < TPB / 32; k++) v += wsum[k];
        atomicAdd(out + b, -0.5f * v);  // ordered-pair sum / 2, negated
    }
}

extern "C" void kernel_launch(void* const* d_in, const int* in_sizes, int n_in,
                              void* d_out, int out_size) {
    const float* x = (const float*)d_in[0];
    float* out = (float*)d_out;

    cudaMemsetAsync(out, 0, NB * sizeof(float));

    dim3 grid(NCHUNK, NCHUNK + 1, NB);  // (16, 17, 4); y==16 row = harmonic
    lj_fused_kernel<<<grid, TPB>>>(x, out);
}

// round 3
// speedup vs baseline: 1.7680x; 1.3387x over previous
#include <cuda_runtime.h>

// LJ_8718783611256: log_prob = -(LJ pair potential + harmonic confinement)
// x: (4, 2048, 3) float32, out: (4,) float32
//
// R3: exploit i<->j symmetry — only upper-triangle tile blocks (bx <= by),
// off-diag weight 1.0, diagonal (full tile, guarded) weight 0.5.
// Packed f32x2 math, fused harmonic, memset-init + atomicAdd.

#define NB      4
#define NPTS    2048
#define TPB     128          // threads per block == i-rows per tile
#define JT      128          // j-tile size
#define NCHUNK  (NPTS / JT)  // 16
#define NTRI    (NCHUNK * (NCHUNK + 1) / 2)  // 136

typedef unsigned long long ull;

#define FMA2(d, a, b, c) \
    asm("fma.rn.f32x2 %0, %1, %2, %3;" : "=l"(d) : "l"(a), "l"(b), "l"(c))
#define MUL2(d, a, b) \
    asm("mul.rn.f32x2 %0, %1, %2;" : "=l"(d) : "l"(a), "l"(b))
#define ADD2(d, a, b) \
    asm("add.rn.f32x2 %0, %1, %2;" : "=l"(d) : "l"(a), "l"(b))
#define PACK2(d, lo, hi) \
    asm("mov.b64 %0, {%1, %2};" : "=l"(d) : "f"(lo), "f"(hi))
#define UNPACK2(lo, hi, d) \
    asm("mov.b64 {%0, %1}, %2;" : "=f"(lo), "=f"(hi) : "l"(d))
#define RCP(d, s) \
    asm("rcp.approx.f32 %0, %1;" : "=f"(d) : "f"(s))

template <bool DIAG>
__device__ __forceinline__ void lj_loop(const ull* __restrict__ sx2,
                                        const ull* __restrict__ sy2,
                                        const ull* __restrict__ sz2,
                                        ull xi2, ull yi2, ull zi2,
                                        ull& a12, ull& a6) {
    const ull neg1 = 0xBF800000BF800000ULL;  // (-1.0f, -1.0f)
    #pragma unroll 8
    for (int k = 0; k < JT / 2; k++) {
        ull px = sx2[k];
        ull py = sy2[k];
        ull pz = sz2[k];
        ull dx, dy, dz, sq, t2, i3, inv2;
        FMA2(dx, px, neg1, xi2);             // xi - px   (x2)
        FMA2(dy, py, neg1, yi2);
        FMA2(dz, pz, neg1, zi2);
        MUL2(sq, dx, dx);
        FMA2(sq, dy, dy, sq);
        FMA2(sq, dz, dz, sq);                // squared distance (x2)
        float s0, s1;
        UNPACK2(s0, s1, sq);
        if (DIAG) {
            // i == j gives sq == 0 exactly; push to huge -> rcp underflows -> 0
            s0 = (s0 == 0.f) ? 3e38f : s0;
            s1 = (s1 == 0.f) ? 3e38f : s1;
        }
        float i0, i1;
        RCP(i0, s0);
        RCP(i1, s1);
        PACK2(inv2, i0, i1);
        MUL2(t2, inv2, inv2);
        MUL2(i3, t2, inv2);                  // d^-6 (x2)
        FMA2(a12, i3, i3, a12);              // sum d^-12
        ADD2(a6, i3, a6);                    // sum d^-6
    }
}

__global__ __launch_bounds__(TPB) void lj_tri_kernel(const float* __restrict__ x,
                                                     float* __restrict__ out) {
    const int b = blockIdx.z;
    const float* xb = x + b * NPTS * 3;
    const int t = threadIdx.x;
    const int w = t >> 5, lane = t & 31;

    // ---------------- harmonic block (blockIdx.x == NTRI) ----------------
    if (blockIdx.x == NTRI) {
        float sx = 0.f, sy = 0.f, sz = 0.f, s2 = 0.f;
        for (int i = t; i < NPTS; i += TPB) {
            float px = xb[3 * i + 0];
            float py = xb[3 * i + 1];
            float pz = xb[3 * i + 2];
            sx += px; sy += py; sz += pz;
            s2 = fmaf(px, px, s2);
            s2 = fmaf(py, py, s2);
            s2 = fmaf(pz, pz, s2);
        }
        #pragma unroll
        for (int o = 16; o; o >>= 1) {
            sx += __shfl_xor_sync(0xffffffffu, sx, o);
            sy += __shfl_xor_sync(0xffffffffu, sy, o);
            sz += __shfl_xor_sync(0xffffffffu, sz, o);
            s2 += __shfl_xor_sync(0xffffffffu, s2, o);
        }
        __shared__ float red[4][TPB / 32];
        if (lane == 0) { red[0][w] = sx; red[1][w] = sy; red[2][w] = sz; red[3][w] = s2; }
        __syncthreads();
        if (t == 0) {
            float tx = 0.f, ty = 0.f, tz = 0.f, t2 = 0.f;
            #pragma unroll
            for (int k = 0; k < TPB / 32; k++) {
                tx += red[0][k]; ty += red[1][k]; tz += red[2][k]; t2 += red[3][k];
            }
            float com2 = (tx * tx + ty * ty + tz * tz) * (1.0f / NPTS);
            float harm = 0.25f * (t2 - com2);  // 0.5 * k(=0.5) * sum((x-com)^2)
            atomicAdd(out + b, -harm);
        }
        return;
    }

    // ---------------- triangle tile mapping ----------------
    // linear tile id -> (bx, by) with bx <= by, by = i-tile, bx = j-tile
    const int tid = blockIdx.x;
    int by = (int)((sqrtf(8.0f * tid + 1.0f) - 1.0f) * 0.5f);
    while ((by + 1) * (by + 2) / 2 <= tid) by++;
    while (by * (by + 1) / 2 > tid) by--;
    const int bx = tid - by * (by + 1) / 2;
    const bool diag = (bx == by);

    // ---------------- LJ tile ----------------
    __shared__ float shx[JT], shy[JT], shz[JT];
    const int j0 = bx * JT;
    {
        const float* p = xb + (j0 + t) * 3;
        shx[t] = p[0];
        shy[t] = p[1];
        shz[t] = p[2];
    }
    __syncthreads();

    const int i = by * TPB + t;
    const float xi = xb[3 * i + 0];
    const float yi = xb[3 * i + 1];
    const float zi = xb[3 * i + 2];
    ull xi2, yi2, zi2;
    PACK2(xi2, xi, xi);
    PACK2(yi2, yi, yi);
    PACK2(zi2, zi, zi);

    ull a12 = 0ull, a6 = 0ull;
    const ull* sx2 = (const ull*)shx;
    const ull* sy2 = (const ull*)shy;
    const ull* sz2 = (const ull*)shz;

    if (diag)
        lj_loop<true>(sx2, sy2, sz2, xi2, yi2, zi2, a12, a6);
    else
        lj_loop<false>(sx2, sy2, sz2, xi2, yi2, zi2, a12, a6);

    float a12l, a12h, a6l, a6h;
    UNPACK2(a12l, a12h, a12);
    UNPACK2(a6l, a6h, a6);
    float pot = 4.0f * ((a12l + a12h) - (a6l + a6h));

    #pragma unroll
    for (int o = 16; o; o >>= 1)
        pot += __shfl_xor_sync(0xffffffffu, pot, o);

    __shared__ float wsum[TPB / 32];
    if (lane == 0) wsum[w] = pot;
    __syncthreads();

    if (t == 0) {
        float v = 0.f;
        #pragma unroll
        for (int k = 0; k < TPB / 32; k++) v += wsum[k];
        // triangle sum: off-diag tiles count each unordered pair once (weight 1);
        // diagonal tiles computed full ordered (weight 0.5). Negate for log_prob.
        const float wgt = diag ? 0.5f : 1.0f;
        atomicAdd(out + b, -wgt * v);
    }
}

extern "C" void kernel_launch(void* const* d_in, const int* in_sizes, int n_in,
                              void* d_out, int out_size) {
    const float* x = (const float*)d_in[0];
    float* out = (float*)d_out;

    cudaMemsetAsync(out, 0, NB * sizeof(float));

    dim3 grid(NTRI + 1, 1, NB);  // 136 pair tiles + 1 harmonic block, x4 batches
    lj_tri_kernel<<<grid, TPB>>>(x, out);
}